// round 15
// baseline (speedup 1.0000x reference)
#include <cuda_runtime.h>
#include <cuda_bf16.h>
#include <cstdint>
#include <cstddef>

#define DIMM   1024
#define NHEADS 16
#define HD     64
#define BB     4
#define SS     2048
#define MTOT   (BB * SS)      // 8192
#define NQKV   (3 * DIMM)     // 3072

typedef __nv_bfloat16 bf16;

// ---------------- scratch (__device__ globals; no allocation) ----------------
__device__ bf16 g_xh[(size_t)MTOT * DIMM], g_xl[(size_t)MTOT * DIMM];
__device__ bf16 g_ah[(size_t)MTOT * DIMM], g_al[(size_t)MTOT * DIMM];
__device__ bf16 g_wqh[(size_t)NQKV * DIMM], g_wql[(size_t)NQKV * DIMM]; // [N,K]
__device__ bf16 g_woh[(size_t)DIMM * DIMM], g_wol[(size_t)DIMM * DIMM]; // [N,K]
// head-major [b,h,s,d] split Q/K/V (Q pre-scaled by 0.125*log2e)
__device__ bf16 g_q2h[(size_t)MTOT * DIMM], g_q2l[(size_t)MTOT * DIMM];
__device__ bf16 g_k2h[(size_t)MTOT * DIMM], g_k2l[(size_t)MTOT * DIMM];
__device__ bf16 g_v2h[(size_t)MTOT * DIMM], g_v2l[(size_t)MTOT * DIMM];

// ---------------- helpers ----------------
__device__ __forceinline__ float ex2f(float x) {
    float r; asm("ex2.approx.ftz.f32 %0, %1;" : "=f"(r) : "f"(x)); return r;
}
__device__ __forceinline__ uint32_t s2u(const void* p) {
    uint32_t a;
    asm("{ .reg .u64 t; cvta.to.shared.u64 t, %1; cvt.u32.u64 %0, t; }" : "=r"(a) : "l"(p));
    return a;
}
__device__ __forceinline__ void mma16816(float* c, const uint32_t* a, const uint32_t* b) {
    asm volatile("mma.sync.aligned.m16n8k16.row.col.f32.bf16.bf16.f32 "
        "{%0,%1,%2,%3}, {%4,%5,%6,%7}, {%8,%9}, {%0,%1,%2,%3};"
        : "+f"(c[0]), "+f"(c[1]), "+f"(c[2]), "+f"(c[3])
        : "r"(a[0]), "r"(a[1]), "r"(a[2]), "r"(a[3]), "r"(b[0]), "r"(b[1]));
}
__device__ __forceinline__ void ldsm4(uint32_t* r, uint32_t addr) {
    asm volatile("ldmatrix.sync.aligned.m8n8.x4.shared.b16 {%0,%1,%2,%3}, [%4];"
        : "=r"(r[0]), "=r"(r[1]), "=r"(r[2]), "=r"(r[3]) : "r"(addr));
}
__device__ __forceinline__ void ldsm4t(uint32_t* r, uint32_t addr) {
    asm volatile("ldmatrix.sync.aligned.m8n8.x4.trans.shared.b16 {%0,%1,%2,%3}, [%4];"
        : "=r"(r[0]), "=r"(r[1]), "=r"(r[2]), "=r"(r[3]) : "r"(addr));
}
// pack {lo, hi} fp32 -> bf16x2 (lo in low half)
__device__ __forceinline__ uint32_t packbf(float lo, float hi) {
    uint32_t r; asm("cvt.rn.bf16x2.f32 %0, %1, %2;" : "=r"(r) : "f"(hi), "f"(lo)); return r;
}
__device__ __forceinline__ float u2f(uint32_t x) { return __uint_as_float(x); }

// ---------------------------------------------------------------------------
// Split fp32 -> (bf16 hi, bf16 lo)
// ---------------------------------------------------------------------------
__global__ __launch_bounds__(256) void split_kernel(
    const float* __restrict__ in, bf16* __restrict__ oh,
    bf16* __restrict__ ol, int n4)
{
    int i = blockIdx.x * 256 + threadIdx.x;
    if (i >= n4) return;
    float4 v = ((const float4*)in)[i];
    bf16 h0 = __float2bfloat16(v.x), h1 = __float2bfloat16(v.y);
    bf16 h2 = __float2bfloat16(v.z), h3 = __float2bfloat16(v.w);
    ((__nv_bfloat162*)oh)[2 * i]     = __nv_bfloat162(h0, h1);
    ((__nv_bfloat162*)oh)[2 * i + 1] = __nv_bfloat162(h2, h3);
    ((__nv_bfloat162*)ol)[2 * i]     = __nv_bfloat162(
        __float2bfloat16(v.x - __bfloat162float(h0)),
        __float2bfloat16(v.y - __bfloat162float(h1)));
    ((__nv_bfloat162*)ol)[2 * i + 1] = __nv_bfloat162(
        __float2bfloat16(v.z - __bfloat162float(h2)),
        __float2bfloat16(v.w - __bfloat162float(h3)));
}

// ---------------------------------------------------------------------------
// Split + transpose: fp32 [K,N] row-major -> bf16 [N,K] row-major (hi/lo)
// ---------------------------------------------------------------------------
__global__ __launch_bounds__(256) void tsplit_kernel(
    const float* __restrict__ in, bf16* __restrict__ oh,
    bf16* __restrict__ ol, int K, int N)
{
    __shared__ float tile[32][33];
    const int bn = blockIdx.x * 32, bk = blockIdx.y * 32;
    const int tx = threadIdx.x & 31, ty = threadIdx.x >> 5;
#pragma unroll
    for (int i = 0; i < 4; i++)
        tile[ty + 8 * i][tx] = in[(size_t)(bk + ty + 8 * i) * N + bn + tx];
    __syncthreads();
#pragma unroll
    for (int i = 0; i < 4; i++) {
        const int n = bn + ty + 8 * i, k = bk + tx;
        float v = tile[tx][ty + 8 * i];
        bf16 h = __float2bfloat16(v);
        oh[(size_t)n * K + k] = h;
        ol[(size_t)n * K + k] = __float2bfloat16(v - __bfloat162float(h));
    }
}

// ---------------------------------------------------------------------------
// HMMA bf16-split GEMM, K=1024 fixed. 128x128 tile, BK=64.
// 4 warps (2x2), warp tile 64x64 (m=4 x n=8 MMAs) for 1.5x better
// ldmatrix amortization (smem-crossbar was the measured bound).
// 3-slot cp.async ring, one __syncthreads per stage, smem-staged epilogue.
// MODE 1: fp32 C + bias. MODE 2: fused head-major QKV hi/lo split epilogue.
// Dynamic smem: 3 slots x (A 18432 + B 18432) = 110592 B. 128 thr, occ 2.
// ---------------------------------------------------------------------------
template <int MODE>
__global__ __launch_bounds__(128, 2) void gemm_mma(
    const bf16* __restrict__ Ah, const bf16* __restrict__ Al,
    const bf16* __restrict__ Bh, const bf16* __restrict__ Bl,
    const float* __restrict__ bias, float* __restrict__ C,
    bf16* __restrict__ Q2h, bf16* __restrict__ Q2l,
    bf16* __restrict__ K2h, bf16* __restrict__ K2l,
    bf16* __restrict__ V2h, bf16* __restrict__ V2l,
    int M, int N)
{
    constexpr int K = 1024;
    constexpr int KC = 16;        // 64-K chunks per region
    constexpr int St = 3 * KC;    // 48 stages
    constexpr uint32_t SLOT = 36864;

    extern __shared__ char sm[];
    const uint32_t smb = s2u(sm);
    const int tid = threadIdx.x, lane = tid & 31, wid = tid >> 5;
    const int wr = wid & 1, wc = wid >> 1;    // 2 x 2 warps, 64x64 each
    const int bx = blockIdx.x, by = blockIdx.y;

    float acc[4][8][4];
#pragma unroll
    for (int m = 0; m < 4; m++)
#pragma unroll
        for (int n = 0; n < 8; n++)
#pragma unroll
            for (int e = 0; e < 4; e++) acc[m][n][e] = 0.f;

    const uint32_t a_row = wr * 64 + ((lane >> 3) & 1) * 8 + (lane & 7);
    const uint32_t a_colb = (lane >> 4) * 16;
    const uint32_t b_row = wc * 64 + (lane >> 4) * 8 + (lane & 7);
    const uint32_t b_colb = ((lane >> 3) & 1) * 16;
    const uint32_t aoff = a_row * 144 + a_colb;
    const uint32_t boff = 18432 + b_row * 144 + b_colb;

#define ISSUE_LOAD(s_)                                                            \
    {                                                                             \
        const int s__ = (s_);                                                     \
        const int region = s__ >> 4;                                              \
        const int k0 = (s__ & 15) * 64;                                           \
        const bf16* Ag = (region == 1) ? Al : Ah;                                 \
        const bf16* Bg = (region == 2) ? Bl : Bh;                                 \
        const uint32_t sb = smb + (uint32_t)(s__ % 3) * SLOT;                     \
        _Pragma("unroll")                                                         \
        for (int i = 0; i < 8; i++) {                                             \
            const int chunk = tid + i * 128;                                      \
            const int row = chunk >> 3, seg = chunk & 7;                          \
            uint32_t da = sb + row * 144 + seg * 16;                              \
            const void* ga = Ag + (size_t)(by * 128 + row) * K + k0 + seg * 8;    \
            asm volatile("cp.async.cg.shared.global [%0], [%1], 16;"              \
                         :: "r"(da), "l"(ga));                                    \
            uint32_t db = sb + 18432 + row * 144 + seg * 16;                      \
            const void* gb = Bg + (size_t)(bx * 128 + row) * K + k0 + seg * 8;    \
            asm volatile("cp.async.cg.shared.global [%0], [%1], 16;"              \
                         :: "r"(db), "l"(gb));                                    \
        }                                                                         \
        asm volatile("cp.async.commit_group;" ::: "memory");                      \
    }

    ISSUE_LOAD(0); ISSUE_LOAD(1);

    for (int s = 0; s < St; s++) {
        if (s + 1 < St) asm volatile("cp.async.wait_group 1;" ::: "memory");
        else            asm volatile("cp.async.wait_group 0;" ::: "memory");
        __syncthreads();
        if (s + 2 < St) ISSUE_LOAD(s + 2);

        const uint32_t sb = smb + (uint32_t)(s % 3) * SLOT;
        const uint32_t abase = sb + aoff;
        const uint32_t bbase = sb + boff;

#pragma unroll
        for (int kk = 0; kk < 4; kk++) {
            uint32_t a[4][4], b[8][2];
#pragma unroll
            for (int m = 0; m < 4; m++)
                ldsm4(a[m], abase + m * 16 * 144 + kk * 32);
#pragma unroll
            for (int p = 0; p < 4; p++) {
                uint32_t r[4];
                ldsm4(r, bbase + p * 16 * 144 + kk * 32);
                b[2 * p][0] = r[0]; b[2 * p][1] = r[1];
                b[2 * p + 1][0] = r[2]; b[2 * p + 1][1] = r[3];
            }
#pragma unroll
            for (int m = 0; m < 4; m++)
#pragma unroll
                for (int n = 0; n < 8; n++)
                    mma16816(acc[m][n], a[m], b[n]);
        }
    }
#undef ISSUE_LOAD

    // ---- epilogue: stage C tile in smem (fp32 128x132), write coalesced ----
    __syncthreads();
    float* cs = (float*)sm;
#pragma unroll
    for (int m = 0; m < 4; m++) {
        const int r0 = wr * 64 + m * 16 + (lane >> 2);
#pragma unroll
        for (int n = 0; n < 8; n++) {
            const int c0 = wc * 64 + n * 8 + 2 * (lane & 3);
#pragma unroll
            for (int half = 0; half < 2; half++) {
                cs[(r0 + half * 8) * 132 + c0]     = acc[m][n][half * 2];
                cs[(r0 + half * 8) * 132 + c0 + 1] = acc[m][n][half * 2 + 1];
            }
        }
    }
    __syncthreads();

    if (MODE == 2) {
        const float cq = 0.125f * 1.44269504088896340736f;
        const int region = (bx * 128) >> 10;
#pragma unroll
        for (int w = 0; w < 64; w++) {
            const int task = wid + w * 4;       // 0..255
            const int r = task >> 1, hh = task & 1;
            const int grow = by * 128 + r;
            const int b_ = grow >> 11, s_ = grow & (SS - 1);
            const int head = ((bx * 128 + hh * 64) >> 6) & (NHEADS - 1);
            float vx = cs[r * 132 + hh * 64 + 2 * lane];
            float vy = cs[r * 132 + hh * 64 + 2 * lane + 1];
            if (region == 0) { vx *= cq; vy *= cq; }
            const uint32_t hp = packbf(vx, vy);
            const uint32_t lp = packbf(vx - u2f(hp << 16), vy - u2f(hp & 0xffff0000u));
            bf16* oh = (region == 0) ? Q2h : (region == 1) ? K2h : V2h;
            bf16* ol = (region == 0) ? Q2l : (region == 1) ? K2l : V2l;
            const size_t oi = ((size_t)(b_ * NHEADS + head) * SS + s_) * HD;
            ((uint32_t*)(oh + oi))[lane] = hp;
            ((uint32_t*)(ol + oi))[lane] = lp;
        }
    } else {
#pragma unroll
        for (int i = 0; i < 32; i++) {
            const int r = wid * 32 + i;
            float4 v = *(float4*)&cs[r * 132 + lane * 4];
            const int col = bx * 128 + lane * 4;
            if (MODE == 1) {
                float4 bv = *(const float4*)&bias[col];
                v.x += bv.x; v.y += bv.y; v.z += bv.z; v.w += bv.w;
            }
            *(float4*)&C[(size_t)(by * 128 + r) * N + col] = v;
        }
    }
}

// ---------------------------------------------------------------------------
// HMMA flash attention (validated round 6/7). CTA = 128 q-rows of one (b,h).
// ---------------------------------------------------------------------------
__global__ __launch_bounds__(128, 2) void flash_mma(
    const bf16* __restrict__ Qh, const bf16* __restrict__ Ql,
    const bf16* __restrict__ Kh, const bf16* __restrict__ Kl,
    const bf16* __restrict__ Vh, const bf16* __restrict__ Vl,
    bf16* __restrict__ Oh, bf16* __restrict__ Ol)
{
    extern __shared__ char sm[];
    const int tid = threadIdx.x, lane = tid & 31, wid = tid >> 5;
    const int qt = blockIdx.x, h = blockIdx.y, b = blockIdx.z;
    const size_t bh = (size_t)(b * NHEADS + h) * SS;
    const uint32_t smb = s2u(sm);

    {
        const bf16* q0 = Qh + (bh + qt * 128) * HD;
        const bf16* q1 = Ql + (bh + qt * 128) * HD;
#pragma unroll
        for (int i = 0; i < 8; i++) {
            const int c = tid + i * 128;
            const int row = c >> 3, seg = c & 7;
            uint32_t d0 = smb + row * 144 + seg * 16;
            const void* s0 = q0 + (size_t)row * HD + seg * 8;
            asm volatile("cp.async.cg.shared.global [%0], [%1], 16;" :: "r"(d0), "l"(s0));
            uint32_t d1 = smb + 18432 + row * 144 + seg * 16;
            const void* s1 = q1 + (size_t)row * HD + seg * 8;
            asm volatile("cp.async.cg.shared.global [%0], [%1], 16;" :: "r"(d1), "l"(s1));
        }
        asm volatile("cp.async.commit_group;" ::: "memory");
        asm volatile("cp.async.wait_group 0;" ::: "memory");
        __syncthreads();
    }
    uint32_t qfh[2][4][4], qfl[2][4][4];
    {
        const uint32_t arow = wid * 32 + ((lane >> 3) & 1) * 8 + (lane & 7);
        const uint32_t acolb = (lane >> 4) * 16;
#pragma unroll
        for (int m = 0; m < 2; m++)
#pragma unroll
            for (int kk = 0; kk < 4; kk++) {
                ldsm4(qfh[m][kk], smb + (arow + m * 16) * 144 + acolb + kk * 32);
                ldsm4(qfl[m][kk], smb + 18432 + (arow + m * 16) * 144 + acolb + kk * 32);
            }
    }
    __syncthreads();

    float o[2][8][4];
#pragma unroll
    for (int m = 0; m < 2; m++)
#pragma unroll
        for (int n = 0; n < 8; n++)
#pragma unroll
            for (int e = 0; e < 4; e++) o[m][n][e] = 0.f;
    float rm[2][2] = {{-1e30f, -1e30f}, {-1e30f, -1e30f}};
    float rl[2][2] = {{0.f, 0.f}, {0.f, 0.f}};

#define ISSUE_KV(t_)                                                              \
    do {                                                                          \
        const int t__ = (t_);                                                     \
        const uint32_t base_ = smb + (t__ & 1) * 36864;                           \
        const size_t off_ = (bh + (size_t)t__ * 64) * HD;                         \
        const bf16* sA[4] = {Kh + off_, Kl + off_, Vh + off_, Vl + off_};         \
        _Pragma("unroll")                                                         \
        for (int a = 0; a < 4; a++) {                                             \
            _Pragma("unroll")                                                     \
            for (int i = 0; i < 4; i++) {                                         \
                const int c = tid + i * 128;                                      \
                const int row = c >> 3, seg = c & 7;                              \
                uint32_t dst = base_ + a * 9216 + row * 144 + seg * 16;           \
                const void* src = sA[a] + (size_t)row * HD + seg * 8;             \
                asm volatile("cp.async.cg.shared.global [%0], [%1], 16;"          \
                             :: "r"(dst), "l"(src));                              \
            }                                                                     \
        }                                                                         \
        asm volatile("cp.async.commit_group;" ::: "memory");                      \
    } while (0)

    ISSUE_KV(0);

    const uint32_t brow = (lane >> 4) * 8 + (lane & 7);
    const uint32_t bcolb = ((lane >> 3) & 1) * 16;
    const uint32_t vrowi = ((lane >> 3) & 1) * 8 + (lane & 7);
    const uint32_t vcoli = (lane >> 4);

    for (int t = 0; t < 32; t++) {
        if (t + 1 < 32) {
            ISSUE_KV(t + 1);
            asm volatile("cp.async.wait_group 1;" ::: "memory");
        } else {
            asm volatile("cp.async.wait_group 0;" ::: "memory");
        }
        __syncthreads();

        const uint32_t base = smb + (t & 1) * 36864;
        const uint32_t KHb = base, KLb = base + 9216;
        const uint32_t VHb = base + 18432, VLb = base + 27648;

        float s[2][8][4];
#pragma unroll
        for (int m = 0; m < 2; m++)
#pragma unroll
            for (int n = 0; n < 8; n++)
#pragma unroll
                for (int e = 0; e < 4; e++) s[m][n][e] = 0.f;

#pragma unroll
        for (int kk = 0; kk < 4; kk++) {
            uint32_t kb[8][2];
#pragma unroll
            for (int p = 0; p < 4; p++) {
                uint32_t r[4];
                ldsm4(r, KHb + (p * 16 + brow) * 144 + bcolb + kk * 32);
                kb[2 * p][0] = r[0]; kb[2 * p][1] = r[1];
                kb[2 * p + 1][0] = r[2]; kb[2 * p + 1][1] = r[3];
            }
#pragma unroll
            for (int m = 0; m < 2; m++)
#pragma unroll
                for (int n = 0; n < 8; n++) {
                    mma16816(s[m][n], qfh[m][kk], kb[n]);
                    mma16816(s[m][n], qfl[m][kk], kb[n]);
                }
#pragma unroll
            for (int p = 0; p < 4; p++) {
                uint32_t r[4];
                ldsm4(r, KLb + (p * 16 + brow) * 144 + bcolb + kk * 32);
                kb[2 * p][0] = r[0]; kb[2 * p][1] = r[1];
                kb[2 * p + 1][0] = r[2]; kb[2 * p + 1][1] = r[3];
            }
#pragma unroll
            for (int m = 0; m < 2; m++)
#pragma unroll
                for (int n = 0; n < 8; n++)
                    mma16816(s[m][n], qfh[m][kk], kb[n]);
        }

#pragma unroll
        for (int m = 0; m < 2; m++)
#pragma unroll
            for (int eh = 0; eh < 2; eh++) {
                float mx = -1e30f;
#pragma unroll
                for (int n = 0; n < 8; n++) {
                    mx = fmaxf(mx, s[m][n][eh * 2]);
                    mx = fmaxf(mx, s[m][n][eh * 2 + 1]);
                }
                mx = fmaxf(mx, __shfl_xor_sync(0xffffffffu, mx, 1));
                mx = fmaxf(mx, __shfl_xor_sync(0xffffffffu, mx, 2));
                const float newm = fmaxf(rm[m][eh], mx);
                const float corr = ex2f(rm[m][eh] - newm);
                rm[m][eh] = newm;
                float sum = 0.f;
#pragma unroll
                for (int n = 0; n < 8; n++) {
                    float p0 = ex2f(s[m][n][eh * 2] - newm);
                    float p1 = ex2f(s[m][n][eh * 2 + 1] - newm);
                    s[m][n][eh * 2] = p0; s[m][n][eh * 2 + 1] = p1;
                    sum += p0 + p1;
                }
                sum += __shfl_xor_sync(0xffffffffu, sum, 1);
                sum += __shfl_xor_sync(0xffffffffu, sum, 2);
                rl[m][eh] = rl[m][eh] * corr + sum;
#pragma unroll
                for (int n = 0; n < 8; n++) {
                    o[m][n][eh * 2] *= corr;
                    o[m][n][eh * 2 + 1] *= corr;
                }
            }

#pragma unroll
        for (int kk = 0; kk < 4; kk++) {
            uint32_t ph[2][4], pl[2][4];
#pragma unroll
            for (int m = 0; m < 2; m++)
#pragma unroll
                for (int half = 0; half < 2; half++)
#pragma unroll
                    for (int eh = 0; eh < 2; eh++) {
                        const float p0 = s[m][2 * kk + half][eh * 2];
                        const float p1 = s[m][2 * kk + half][eh * 2 + 1];
                        const uint32_t hp = packbf(p0, p1);
                        const float h0 = u2f(hp << 16), h1 = u2f(hp & 0xffff0000u);
                        ph[m][half * 2 + eh] = hp;
                        pl[m][half * 2 + eh] = packbf(p0 - h0, p1 - h1);
                    }

            uint32_t vb[8][2];
#pragma unroll
            for (int g = 0; g < 4; g++) {
                uint32_t r[4];
                ldsm4t(r, VHb + (kk * 16 + vrowi) * 144 + (g * 2 + vcoli) * 16);
                vb[2 * g][0] = r[0]; vb[2 * g][1] = r[1];
                vb[2 * g + 1][0] = r[2]; vb[2 * g + 1][1] = r[3];
            }
#pragma unroll
            for (int m = 0; m < 2; m++)
#pragma unroll
                for (int n = 0; n < 8; n++) {
                    mma16816(o[m][n], ph[m], vb[n]);
                    mma16816(o[m][n], pl[m], vb[n]);
                }
#pragma unroll
            for (int g = 0; g < 4; g++) {
                uint32_t r[4];
                ldsm4t(r, VLb + (kk * 16 + vrowi) * 144 + (g * 2 + vcoli) * 16);
                vb[2 * g][0] = r[0]; vb[2 * g][1] = r[1];
                vb[2 * g + 1][0] = r[2]; vb[2 * g + 1][1] = r[3];
            }
#pragma unroll
            for (int m = 0; m < 2; m++)
#pragma unroll
                for (int n = 0; n < 8; n++)
                    mma16816(o[m][n], ph[m], vb[n]);
        }
        __syncthreads();
    }
#undef ISSUE_KV

#pragma unroll
    for (int m = 0; m < 2; m++)
#pragma unroll
        for (int eh = 0; eh < 2; eh++) {
            const float inv = 1.f / rl[m][eh];
            const int gs = qt * 128 + wid * 32 + m * 16 + (lane >> 2) + eh * 8;
            const size_t rowbase =
                ((size_t)(b * SS) + h * 128 + (gs >> 4)) * DIMM + (gs & 15) * HD;
#pragma unroll
            for (int n = 0; n < 8; n++) {
                const int d = n * 8 + 2 * (lane & 3);
                const float p0 = o[m][n][eh * 2] * inv;
                const float p1 = o[m][n][eh * 2 + 1] * inv;
                const uint32_t hp = packbf(p0, p1);
                const float h0 = u2f(hp << 16), h1 = u2f(hp & 0xffff0000u);
                const uint32_t lp = packbf(p0 - h0, p1 - h1);
                *(uint32_t*)(Oh + rowbase + d) = hp;
                *(uint32_t*)(Ol + rowbase + d) = lp;
            }
        }
}

// ---------------------------------------------------------------------------
// Launch
// ---------------------------------------------------------------------------
extern "C" void kernel_launch(void* const* d_in, const int* in_sizes, int n_in,
                              void* d_out, int out_size)
{
    const float* x     = (const float*)d_in[0];
    const float* w_qkv = (const float*)d_in[1];   // [1024,3072] = [K,N]
    const float* w_out = (const float*)d_in[2];   // [1024,1024]
    const float* b_out = (const float*)d_in[3];
    float* out = (float*)d_out;

    bf16 *xh, *xl, *ah, *al, *wqh, *wql, *woh, *wol;
    bf16 *q2h, *q2l, *k2h, *k2l, *v2h, *v2l;
    cudaGetSymbolAddress((void**)&xh, g_xh);   cudaGetSymbolAddress((void**)&xl, g_xl);
    cudaGetSymbolAddress((void**)&ah, g_ah);   cudaGetSymbolAddress((void**)&al, g_al);
    cudaGetSymbolAddress((void**)&wqh, g_wqh); cudaGetSymbolAddress((void**)&wql, g_wql);
    cudaGetSymbolAddress((void**)&woh, g_woh); cudaGetSymbolAddress((void**)&wol, g_wol);
    cudaGetSymbolAddress((void**)&q2h, g_q2h); cudaGetSymbolAddress((void**)&q2l, g_q2l);
    cudaGetSymbolAddress((void**)&k2h, g_k2h); cudaGetSymbolAddress((void**)&k2l, g_k2l);
    cudaGetSymbolAddress((void**)&v2h, g_v2h); cudaGetSymbolAddress((void**)&v2l, g_v2l);

    const int GEMM_SMEM = 3 * 36864;   // 110592
    cudaFuncSetAttribute(gemm_mma<1>, cudaFuncAttributeMaxDynamicSharedMemorySize, GEMM_SMEM);
    cudaFuncSetAttribute(gemm_mma<2>, cudaFuncAttributeMaxDynamicSharedMemorySize, GEMM_SMEM);
    cudaFuncSetAttribute(flash_mma, cudaFuncAttributeMaxDynamicSharedMemorySize, 73728);

    // 1) split x ; split+transpose w_qkv
    {
        const int n4 = MTOT * DIMM / 4;
        split_kernel<<<n4 / 256, 256>>>(x, xh, xl, n4);
        tsplit_kernel<<<dim3(NQKV / 32, DIMM / 32), 256>>>(w_qkv, wqh, wql, DIMM, NQKV);
    }
    // 2) QKV = x @ w_qkv with fused head-major hi/lo split epilogue
    gemm_mma<2><<<dim3(NQKV / 128, MTOT / 128), 128, GEMM_SMEM>>>(
        xh, xl, wqh, wql, nullptr, nullptr,
        q2h, q2l, k2h, k2l, v2h, v2l, MTOT, NQKV);

    // 3) HMMA flash attention -> writes g_ah/g_al directly (permuted)
    flash_mma<<<dim3(SS / 128, NHEADS, BB), 128, 73728>>>(
        q2h, q2l, k2h, k2l, v2h, v2l, ah, al);

    // 4) split+transpose w_out ; out = attn @ w_out + b
    tsplit_kernel<<<dim3(DIMM / 32, DIMM / 32), 256>>>(w_out, woh, wol, DIMM, DIMM);
    gemm_mma<1><<<dim3(DIMM / 128, MTOT / 128), 128, GEMM_SMEM>>>(
        ah, al, woh, wol, b_out, out,
        nullptr, nullptr, nullptr, nullptr, nullptr, nullptr, MTOT, DIMM);
}